// round 3
// baseline (speedup 1.0000x reference)
#include <cuda_runtime.h>
#include <math.h>

#define Bn 4
#define Cc 192
#define Dd 4
#define Hh 16
#define Ww 16
#define LL 1024
#define DIN 384
#define DSTATE 64
#define DTRANK 12
#define DCONV 4
#define MM (Bn * LL)    // 4096 rows
#define HIDN (Bn * 48 * LL)

// ---------------- scratch (device globals; no allocation) ----------------
__device__ float g_pooled[Bn * Cc];
__device__ float g_wts[Bn * 3];
__device__ float g_hidp[6 * HIDN];       // conv1 partial sums per chunk
__device__ float g_hid[HIDN];
__device__ float g_offs[Bn * LL * 3];
__device__ float g_xs[MM * Cc];
__device__ float g_xz[MM * 2 * DIN];
__device__ float g_xi[MM * DIN];
__device__ float g_dbl[MM * 140];
__device__ float g_delta[MM * DIN];
__device__ float g_y[MM * DIN];
__device__ float g_p2[Bn * Cc];
__device__ float g_attn[Bn * Cc];
__device__ float g_xT[MM * Cc];          // [b*L + l][c]
__device__ float g_Wcat[Cc * Cc];
__device__ float g_bcat[Cc];
__device__ float g_w1t[27 * 48 * Cc];    // [tap][o][c]

__device__ __forceinline__ float sigmoidf_(float x) { return 1.f / (1.f + expf(-x)); }
__device__ __forceinline__ float geluf_(float x) {
    return 0.5f * x * (1.f + erff(x * 0.70710678118654752440f));
}
__device__ __forceinline__ float softplusf_(float x) {
    return (x > 20.f) ? x : log1pf(expf(x));
}

// ---------------- tiled transpose x: [b][c][l] -> g_xT [b*L+l][c] ----------------
// grid (32 l-tiles, 6 c-tiles, 4 b), block 256
__global__ void xt_kernel(const float* __restrict__ x) {
    __shared__ float tile[32][33];
    int l0 = blockIdx.x * 32, c0 = blockIdx.y * 32, b = blockIdx.z;
    int tx = threadIdx.x & 31, ty = threadIdx.x >> 5;
    #pragma unroll
    for (int i = 0; i < 32; i += 8)
        tile[ty + i][tx] = x[(b * Cc + c0 + ty + i) * LL + l0 + tx];
    __syncthreads();
    #pragma unroll
    for (int i = 0; i < 32; i += 8)
        g_xT[(b * LL + l0 + ty + i) * Cc + c0 + tx] = tile[tx][ty + i];
}

// ---------------- mean over last dim (1024) ----------------
__global__ void mean_kernel(const float* __restrict__ in, float* __restrict__ out) {
    int bc = blockIdx.x;
    const float* p = in + bc * LL;
    float s = 0.f;
    for (int i = threadIdx.x; i < LL; i += 256) s += p[i];
    __shared__ float sm[256];
    sm[threadIdx.x] = s; __syncthreads();
    for (int st = 128; st > 0; st >>= 1) {
        if (threadIdx.x < st) sm[threadIdx.x] += sm[threadIdx.x + st];
        __syncthreads();
    }
    if (threadIdx.x == 0) out[bc] = sm[0] * (1.f / (float)LL);
}

// ---------------- branch gate weights ----------------
__global__ void wts_kernel(const float* __restrict__ wg_w, const float* __restrict__ wg_b) {
    int b = blockIdx.x;
    int i = threadIdx.x >> 5;
    int lane = threadIdx.x & 31;
    float s = 0.f;
    for (int c = lane; c < Cc; c += 32) s += g_pooled[b * Cc + c] * wg_w[i * Cc + c];
    for (int off = 16; off; off >>= 1) s += __shfl_xor_sync(0xffffffffu, s, off);
    __shared__ float lg[3];
    if (lane == 0) lg[i] = s + wg_b[i];
    __syncthreads();
    if (threadIdx.x == 0) {
        float m = fmaxf(lg[0], fmaxf(lg[1], lg[2]));
        float e0 = expf(lg[0] - m), e1 = expf(lg[1] - m), e2 = expf(lg[2] - m);
        float inv = 1.f / (e0 + e1 + e2);
        g_wts[b * 3 + 0] = e0 * inv;
        g_wts[b * 3 + 1] = e1 * inv;
        g_wts[b * 3 + 2] = e2 * inv;
    }
}

// ---------------- build Wcat / bcat ----------------
__global__ void catw_kernel(const float* __restrict__ px_w, const float* __restrict__ px_b,
                            const float* __restrict__ py_w, const float* __restrict__ py_b,
                            const float* __restrict__ pz_w, const float* __restrict__ pz_b) {
    int t = blockIdx.x * 256 + threadIdx.x;
    if (t < Cc * Cc) {
        int o = t / Cc, c = t % Cc;
        const float* src = (o < 64) ? px_w : (o < 128) ? py_w : pz_w;
        g_Wcat[t] = src[(o & 63) * Cc + c];
    }
    if (t < Cc) {
        const float* sb = (t < 64) ? px_b : (t < 128) ? py_b : pz_b;
        g_bcat[t] = sb[t & 63];
    }
}

// ---------------- transpose conv1 weights: [o][c][tap] -> [tap][o][c] ----------------
__global__ void w1t_kernel(const float* __restrict__ w1) {
    int t = blockIdx.x * 256 + threadIdx.x;
    if (t >= 27 * 48 * Cc) return;
    int tap = t / (48 * Cc);
    int rest = t % (48 * Cc);
    int o = rest / Cc, c = rest % Cc;
    g_w1t[t] = w1[(o * Cc + c) * 27 + tap];
}

// ---------------- conv1 partial: grid (128 tiles, 6 chunks); block 128 ----------------
// chunk = kd*2 + c-half. Each block: 32 voxels x 48 outputs over 9 taps x 96 channels.
__global__ void conv1p_kernel(const float* __restrict__ x) {
    __shared__ float sA[32][97];
    __shared__ float sW[48][97];
    int bid = blockIdx.x;
    int b = bid >> 5, z = (bid >> 3) & 3, y0 = (bid & 7) * 2;
    int chunk = blockIdx.y;
    int kd = chunk >> 1, c0 = (chunk & 1) * 96;
    int zz = z + kd - 1;
    bool zok = (zz >= 0) && (zz < Dd);
    int tid = threadIdx.x;
    int lg = tid & 7, og = tid >> 3;
    float acc[4][3] = {};
    for (int t9 = 0; t9 < 9; ++t9) {
        int kh = t9 / 3, kw = t9 % 3;
        #pragma unroll
        for (int t = 0; t < 24; ++t) {
            int idx = tid + t * 128;
            int v = idx & 31, c = idx >> 5;
            int vy = y0 + (v >> 4), vx = v & 15;
            int yy = vy + kh - 1, xx = vx + kw - 1;
            float val = 0.f;
            if (zok && yy >= 0 && yy < Hh && xx >= 0 && xx < Ww)
                val = x[((b * Cc + c0 + c) << 10) + (zz << 8) + (yy << 4) + xx];
            sA[v][c] = val;
        }
        #pragma unroll
        for (int t = 0; t < 36; ++t) {
            int idx = tid + t * 128;
            int o = idx / 96, c = idx % 96;
            sW[o][c] = g_w1t[(kd * 9 + t9) * (48 * Cc) + o * Cc + c0 + c];
        }
        __syncthreads();
        #pragma unroll 8
        for (int c = 0; c < 96; ++c) {
            float a0 = sA[lg * 4 + 0][c], a1 = sA[lg * 4 + 1][c];
            float a2 = sA[lg * 4 + 2][c], a3 = sA[lg * 4 + 3][c];
            float w0 = sW[og * 3 + 0][c], w1v = sW[og * 3 + 1][c], w2v = sW[og * 3 + 2][c];
            acc[0][0] += a0 * w0; acc[0][1] += a0 * w1v; acc[0][2] += a0 * w2v;
            acc[1][0] += a1 * w0; acc[1][1] += a1 * w1v; acc[1][2] += a1 * w2v;
            acc[2][0] += a2 * w0; acc[2][1] += a2 * w1v; acc[2][2] += a2 * w2v;
            acc[3][0] += a3 * w0; acc[3][1] += a3 * w1v; acc[3][2] += a3 * w2v;
        }
        __syncthreads();
    }
    float* dst = g_hidp + chunk * HIDN;
    #pragma unroll
    for (int i = 0; i < 4; ++i) {
        int v = lg * 4 + i;
        int vy = y0 + (v >> 4), vx = v & 15;
        int l = (z << 8) + (vy << 4) + vx;
        #pragma unroll
        for (int j = 0; j < 3; ++j) {
            int o = og * 3 + j;
            dst[((b * 48 + o) << 10) + l] = acc[i][j];
        }
    }
}

// ---------------- reduce partials + bias + gelu -> g_hid ----------------
__global__ void hidred_kernel(const float* __restrict__ b1) {
    int t = blockIdx.x * 256 + threadIdx.x;
    if (t >= HIDN) return;
    int o = (t >> 10) % 48;
    float s = b1[o];
    #pragma unroll
    for (int k = 0; k < 6; ++k) s += g_hidp[k * HIDN + t];
    g_hid[t] = geluf_(s);
}

// ---------------- conv2 tiled: g_hid -> offsets [B,L,3] ----------------
__global__ void conv2_kernel(const float* __restrict__ w2, const float* __restrict__ b2) {
    __shared__ float sH[48 * 162];
    __shared__ float red[2304];
    int bid = blockIdx.x;
    int b = bid >> 6, z = (bid >> 4) & 3, y = bid & 15;
    int tid = threadIdx.x;
    for (int idx = tid; idx < 48 * 162; idx += 144) {
        int c = idx / 162, r = idx % 162;
        int zz = r / 54, yy = (r / 18) % 3, xx = r % 18;
        int gz = z + zz - 1, gy = y + yy - 1, gx = xx - 1;
        float val = 0.f;
        if (gz >= 0 && gz < Dd && gy >= 0 && gy < Hh && gx >= 0 && gx < Ww)
            val = g_hid[((b * 48 + c) << 10) + (gz << 8) + (gy << 4) + gx];
        sH[idx] = val;
    }
    __syncthreads();
    int i = tid % 48, j = tid / 48;
    float wr[27];
    #pragma unroll
    for (int tap = 0; tap < 27; ++tap) wr[tap] = w2[(j * 48 + i) * 27 + tap];
    for (int xp = 0; xp < 16; ++xp) {
        float s = 0.f;
        #pragma unroll
        for (int tap = 0; tap < 27; ++tap) {
            int kd = tap / 9, kh = (tap / 3) % 3, kw = tap % 3;
            s += sH[i * 162 + kd * 54 + kh * 18 + xp + kw] * wr[tap];
        }
        red[(j * 16 + xp) * 48 + i] = s;
    }
    __syncthreads();
    if (tid < 48) {
        int jj = tid >> 4, xp = tid & 15;
        float s = b2[jj];
        #pragma unroll 8
        for (int k = 0; k < 48; ++k) s += red[(jj * 16 + xp) * 48 + k];
        g_offs[(((b << 10) + (z << 8) + (y << 4) + xp)) * 3 + jj] = s;
    }
}

// ---------------- pos-emb grid sample -> g_xs ----------------
__global__ void posemb_kernel() {
    int bl = blockIdx.x;
    int b = bl >> 10;
    int c = threadIdx.x;
    float gx = g_offs[bl * 3 + 0];
    float gy = g_offs[bl * 3 + 1];
    float gz = g_offs[bl * 3 + 2];
    float ixf = ((gx + 1.f) * (float)Ww - 1.f) * 0.5f;
    float iyf = ((gy + 1.f) * (float)Hh - 1.f) * 0.5f;
    float izf = ((gz + 1.f) * (float)Dd - 1.f) * 0.5f;
    float x0 = floorf(ixf), y0 = floorf(iyf), z0 = floorf(izf);
    float pe = 0.f;
    #pragma unroll
    for (int dz = 0; dz < 2; ++dz)
    #pragma unroll
    for (int dy = 0; dy < 2; ++dy)
    #pragma unroll
    for (int dx = 0; dx < 2; ++dx) {
        float xc = x0 + dx, yc = y0 + dy, zc = z0 + dz;
        float wgt = (1.f - fabsf(ixf - xc)) * (1.f - fabsf(iyf - yc)) * (1.f - fabsf(izf - zc));
        bool valid = (xc >= 0.f) && (xc < (float)Ww) && (yc >= 0.f) && (yc < (float)Hh)
                  && (zc >= 0.f) && (zc < (float)Dd);
        int xi_ = (int)fminf(fmaxf(xc, 0.f), (float)(Ww - 1));
        int yi_ = (int)fminf(fmaxf(yc, 0.f), (float)(Hh - 1));
        int zi_ = (int)fminf(fmaxf(zc, 0.f), (float)(Dd - 1));
        int idx = (zi_ * Hh + yi_) * Ww + xi_;
        pe += g_xT[(b * LL + idx) * Cc + c] * wgt * (valid ? 1.f : 0.f);
    }
    g_xs[bl * Cc + c] = pe;
}

// ---------------- tiled GEMM (float4 smem): C[M][N] = A[M][K] * W[N][K]^T ----------------
// grid (M/32, ceil(N/64)); block 128; micro-tile 4x4
// EPI 0: plain store  1: (+bias)*wts += g_xs   2: transposed store [b][n][l]
template<int K, int N, int EPI>
__global__ void gemm_kernel(const float* __restrict__ A, const float* __restrict__ W,
                            float* __restrict__ outp) {
    __shared__ __align__(16) float sA[32][68];
    __shared__ __align__(16) float sW[64][68];
    int m0 = blockIdx.x * 32;
    int n0 = blockIdx.y * 64;
    int tid = threadIdx.x;
    int lg = tid & 7, og = tid >> 3;
    float acc[4][4] = {};
    for (int k0 = 0; k0 < K; k0 += 64) {
        #pragma unroll
        for (int t = 0; t < 16; ++t) {
            int idx = tid + t * 128;
            int r = idx >> 6, c = idx & 63;
            sA[r][c] = A[(m0 + r) * K + k0 + c];
        }
        #pragma unroll
        for (int t = 0; t < 32; ++t) {
            int idx = tid + t * 128;
            int r = idx >> 6, c = idx & 63;
            int n = n0 + r;
            sW[r][c] = (n < N) ? W[n * K + k0 + c] : 0.f;
        }
        __syncthreads();
        #pragma unroll
        for (int k4 = 0; k4 < 16; ++k4) {
            float4 a0 = *(const float4*)&sA[lg * 4 + 0][k4 * 4];
            float4 a1 = *(const float4*)&sA[lg * 4 + 1][k4 * 4];
            float4 a2 = *(const float4*)&sA[lg * 4 + 2][k4 * 4];
            float4 a3 = *(const float4*)&sA[lg * 4 + 3][k4 * 4];
            float4 w0 = *(const float4*)&sW[og * 4 + 0][k4 * 4];
            float4 w1 = *(const float4*)&sW[og * 4 + 1][k4 * 4];
            float4 w2 = *(const float4*)&sW[og * 4 + 2][k4 * 4];
            float4 w3 = *(const float4*)&sW[og * 4 + 3][k4 * 4];
            #define DOT(i, j, av, wv) \
                acc[i][j] += av.x * wv.x; acc[i][j] += av.y * wv.y; \
                acc[i][j] += av.z * wv.z; acc[i][j] += av.w * wv.w;
            DOT(0,0,a0,w0) DOT(0,1,a0,w1) DOT(0,2,a0,w2) DOT(0,3,a0,w3)
            DOT(1,0,a1,w0) DOT(1,1,a1,w1) DOT(1,2,a1,w2) DOT(1,3,a1,w3)
            DOT(2,0,a2,w0) DOT(2,1,a2,w1) DOT(2,2,a2,w2) DOT(2,3,a2,w3)
            DOT(3,0,a3,w0) DOT(3,1,a3,w1) DOT(3,2,a3,w2) DOT(3,3,a3,w3)
            #undef DOT
        }
        __syncthreads();
    }
    #pragma unroll
    for (int i = 0; i < 4; ++i) {
        int l = m0 + lg * 4 + i;
        #pragma unroll
        for (int j = 0; j < 4; ++j) {
            int n = n0 + og * 4 + j;
            if (n < N) {
                if (EPI == 0) {
                    outp[l * N + n] = acc[i][j];
                } else if (EPI == 1) {
                    float wt = g_wts[(l >> 10) * 3 + (n >> 6)];
                    g_xs[l * Cc + n] += (acc[i][j] + g_bcat[n]) * wt;
                } else {
                    outp[(((l >> 10) * Cc + n) << 10) + (l & 1023)] = acc[i][j];
                }
            }
        }
    }
}

// ---------------- depthwise causal conv (k=4) + silu ----------------
__global__ void dwconv_kernel(const float* __restrict__ cw, const float* __restrict__ cb) {
    int t = blockIdx.x * blockDim.x + threadIdx.x;
    if (t >= MM * DIN) return;
    int d = t % DIN; int bl = t / DIN; int l = bl % LL; int b = bl / LL;
    const float* base = g_xz + (b * LL) * (2 * DIN) + d;
    float s = cb[d];
    #pragma unroll
    for (int k = 0; k < DCONV; ++k) {
        int ll = l - (DCONV - 1) + k;
        if (ll >= 0) s += base[ll * (2 * DIN)] * cw[d * DCONV + k];
    }
    g_xi[t] = s * sigmoidf_(s);
}

// ---------------- delta = softplus(dt @ dt_proj_w.T + b) ----------------
__global__ void delta_kernel(const float* __restrict__ dtw, const float* __restrict__ dtb) {
    __shared__ float sdt[DIN * DTRANK];
    int tid = threadIdx.x;
    for (int k = tid; k < DIN * DTRANK; k += 256) sdt[k] = dtw[k];
    __syncthreads();
    int t = blockIdx.x * 256 + tid;
    if (t >= MM * DIN) return;
    int d = t % DIN; int bl = t / DIN;
    const float* row = g_dbl + bl * 140;
    float s = dtb[d];
    #pragma unroll
    for (int r = 0; r < DTRANK; ++r) s += row[r] * sdt[d * DTRANK + r];
    g_delta[t] = softplusf_(s);
}

// ---------------- selective scan + silu(z) gate ----------------
__global__ void scan_kernel(const float* __restrict__ a_log, const float* __restrict__ Dskip) {
    int warp = (blockIdx.x * blockDim.x + threadIdx.x) >> 5;
    int lane = threadIdx.x & 31;
    if (warp >= Bn * DIN) return;
    int b = warp / DIN, d = warp % DIN;
    float a0 = -expf(a_log[d * DSTATE + lane]);
    float a1 = -expf(a_log[d * DSTATE + 32 + lane]);
    float dsk = Dskip[d];
    float h0 = 0.f, h1 = 0.f;
    const float* dptr = g_delta + b * LL * DIN + d;
    const float* uptr = g_xi + b * LL * DIN + d;
    const float* dblb = g_dbl + b * LL * 140;
    const float* zptr = g_xz + b * LL * (2 * DIN) + DIN + d;
    float* yo = g_y + b * LL * DIN + d;
    #pragma unroll 4
    for (int l = 0; l < LL; ++l) {
        float dt = __ldg(dptr + l * DIN);
        float u = __ldg(uptr + l * DIN);
        const float* row = dblb + l * 140;
        float b0 = __ldg(row + 12 + lane), b1v = __ldg(row + 44 + lane);
        float c0 = __ldg(row + 76 + lane), c1 = __ldg(row + 108 + lane);
        float du = dt * u;
        h0 = __expf(dt * a0) * h0 + du * b0;
        h1 = __expf(dt * a1) * h1 + du * b1v;
        float part = h0 * c0 + h1 * c1;
        #pragma unroll
        for (int off = 16; off; off >>= 1) part += __shfl_xor_sync(0xffffffffu, part, off);
        if (lane == 0) {
            float z = __ldg(zptr + l * (2 * DIN));
            yo[l * DIN] = (part + u * dsk) * (z * sigmoidf_(z));
        }
    }
}

// ---------------- channel attention ----------------
__global__ void ca_kernel(const float* __restrict__ w1, const float* __restrict__ b1,
                          const float* __restrict__ w2, const float* __restrict__ b2) {
    int b = blockIdx.x;
    int tid = threadIdx.x;
    __shared__ float p[Cc];
    __shared__ float hid[48];
    p[tid] = g_p2[b * Cc + tid];
    __syncthreads();
    if (tid < 48) {
        const float* wr = w1 + tid * Cc;
        float s = b1[tid];
        for (int k = 0; k < Cc; ++k) s += p[k] * wr[k];
        hid[tid] = geluf_(s);
    }
    __syncthreads();
    const float* wr2 = w2 + tid * 48;
    float s = b2[tid];
    #pragma unroll
    for (int j = 0; j < 48; ++j) s += hid[j] * wr2[j];
    g_attn[b * Cc + tid] = sigmoidf_(s);
}

__global__ void scale_kernel(float* __restrict__ out) {
    int t = blockIdx.x * blockDim.x + threadIdx.x;
    if (t >= Bn * Cc * LL) return;
    out[t] *= g_attn[t / LL];
}

extern "C" void kernel_launch(void* const* d_in, const int* in_sizes, int n_in,
                              void* d_out, int out_size) {
    const float* x         = (const float*)d_in[0];
    const float* px_w      = (const float*)d_in[1];
    const float* px_b      = (const float*)d_in[2];
    const float* py_w      = (const float*)d_in[3];
    const float* py_b      = (const float*)d_in[4];
    const float* pz_w      = (const float*)d_in[5];
    const float* pz_b      = (const float*)d_in[6];
    const float* wg_w      = (const float*)d_in[7];
    const float* wg_b      = (const float*)d_in[8];
    const float* off_w1    = (const float*)d_in[9];
    const float* off_b1    = (const float*)d_in[10];
    const float* off_w2    = (const float*)d_in[11];
    const float* off_b2    = (const float*)d_in[12];
    const float* in_proj_w = (const float*)d_in[13];
    const float* conv_w    = (const float*)d_in[14];
    const float* conv_b    = (const float*)d_in[15];
    const float* x_proj_w  = (const float*)d_in[16];
    const float* dt_proj_w = (const float*)d_in[17];
    const float* dt_proj_b = (const float*)d_in[18];
    const float* A_log     = (const float*)d_in[19];
    const float* D_skip    = (const float*)d_in[20];
    const float* out_proj_w = (const float*)d_in[21];
    const float* ca_w1     = (const float*)d_in[22];
    const float* ca_b1     = (const float*)d_in[23];
    const float* ca_w2     = (const float*)d_in[24];
    const float* ca_b2     = (const float*)d_in[25];
    float* out = (float*)d_out;

    float *g_pooled_p, *g_p2_p, *g_xT_p, *g_xs_p, *g_xz_p, *g_xi_p, *g_dbl_p, *g_y_p, *g_Wcat_p;
    cudaGetSymbolAddress((void**)&g_pooled_p, g_pooled);
    cudaGetSymbolAddress((void**)&g_p2_p, g_p2);
    cudaGetSymbolAddress((void**)&g_xT_p, g_xT);
    cudaGetSymbolAddress((void**)&g_xs_p, g_xs);
    cudaGetSymbolAddress((void**)&g_xz_p, g_xz);
    cudaGetSymbolAddress((void**)&g_xi_p, g_xi);
    cudaGetSymbolAddress((void**)&g_dbl_p, g_dbl);
    cudaGetSymbolAddress((void**)&g_y_p, g_y);
    cudaGetSymbolAddress((void**)&g_Wcat_p, g_Wcat);

    xt_kernel<<<dim3(32, 6, 4), 256>>>(x);
    mean_kernel<<<Bn * Cc, 256>>>(x, g_pooled_p);
    wts_kernel<<<Bn, 96>>>(wg_w, wg_b);
    w1t_kernel<<<(27 * 48 * Cc + 255) / 256, 256>>>(off_w1);
    catw_kernel<<<(Cc * Cc + 255) / 256, 256>>>(px_w, px_b, py_w, py_b, pz_w, pz_b);
    conv1p_kernel<<<dim3(128, 6), 128>>>(x);
    hidred_kernel<<<(HIDN + 255) / 256, 256>>>(off_b1);
    conv2_kernel<<<256, 144>>>(off_w2, off_b2);
    posemb_kernel<<<MM, Cc>>>();
    gemm_kernel<Cc, Cc, 1><<<dim3(MM / 32, 3), 128>>>(g_xT_p, g_Wcat_p, g_xs_p);
    gemm_kernel<Cc, 2 * DIN, 0><<<dim3(MM / 32, 12), 128>>>(g_xs_p, in_proj_w, g_xz_p);
    dwconv_kernel<<<(MM * DIN + 255) / 256, 256>>>(conv_w, conv_b);
    gemm_kernel<DIN, 140, 0><<<dim3(MM / 32, 3), 128>>>(g_xi_p, x_proj_w, g_dbl_p);
    delta_kernel<<<(MM * DIN + 255) / 256, 256>>>(dt_proj_w, dt_proj_b);
    scan_kernel<<<(Bn * DIN * 32 + 127) / 128, 128>>>(A_log, D_skip);
    gemm_kernel<DIN, Cc, 2><<<dim3(MM / 32, 3), 128>>>(g_y_p, out_proj_w, out);
    mean_kernel<<<Bn * Cc, 256>>>(out, g_p2_p);
    ca_kernel<<<Bn, Cc>>>(ca_w1, ca_b1, ca_w2, ca_b2);
    scale_kernel<<<(Bn * Cc * LL + 255) / 256, 256>>>(out);
}

// round 4
// speedup vs baseline: 1.2103x; 1.2103x over previous
#include <cuda_runtime.h>
#include <math.h>

#define Bn 4
#define Cc 192
#define Dd 4
#define Hh 16
#define Ww 16
#define LL 1024
#define DIN 384
#define DSTATE 64
#define DTRANK 12
#define DCONV 4
#define MM (Bn * LL)          // 4096
#define HIDN (Bn * LL * 48)   // 196608

// ---------------- scratch ----------------
__device__ float g_pooled[Bn * Cc];
__device__ float g_wts[Bn * 3];
__device__ float g_hidp[27 * HIDN];
__device__ float g_hidT[HIDN];          // [bl][48]
__device__ float g_offs[Bn * LL * 3];
__device__ float g_xs[MM * Cc];
__device__ float g_xz[MM * 2 * DIN];
__device__ float g_xi[MM * DIN];
__device__ float g_dbl[MM * 140];
__device__ float g_delta[MM * DIN];
__device__ float g_y[MM * DIN];
__device__ float g_p2[Bn * Cc];
__device__ float g_attn[Bn * Cc];
__device__ float g_xT[MM * Cc];         // [bl][c]
// pre-transposed weights [K][N]
__device__ float g_tin[Cc * 768];       // in_proj
__device__ float g_tcat[Cc * Cc];       // branch cat
__device__ float g_bcat[Cc];
__device__ float g_tx[DIN * 192];       // x_proj padded 140->192
__device__ float g_tout[DIN * Cc];      // out_proj
__device__ float g_tw1[27 * Cc * 64];   // conv1 [tap][c][o pad 48->64]

__device__ __forceinline__ float sigmoidf_(float x) { return 1.f / (1.f + expf(-x)); }
__device__ __forceinline__ float geluf_(float x) {
    return 0.5f * x * (1.f + erff(x * 0.70710678118654752440f));
}
__device__ __forceinline__ float softplusf_(float x) {
    return (x > 20.f) ? x : log1pf(expf(x));
}

// ---------------- prep: all weight transposes in one launch ----------------
__global__ void prep_kernel(const float* __restrict__ in_proj_w,
                            const float* __restrict__ px_w, const float* __restrict__ py_w,
                            const float* __restrict__ pz_w,
                            const float* __restrict__ px_b, const float* __restrict__ py_b,
                            const float* __restrict__ pz_b,
                            const float* __restrict__ x_proj_w,
                            const float* __restrict__ out_proj_w,
                            const float* __restrict__ off_w1) {
    int t = blockIdx.x * 256 + threadIdx.x;
    if (t < 147456) { int k = t / 768, n = t % 768; g_tin[t] = in_proj_w[n * Cc + k]; return; }
    t -= 147456;
    if (t < 36864) {
        int k = t / Cc, n = t % Cc; int br = n >> 6, oo = n & 63;
        const float* s = (br == 0) ? px_w : (br == 1) ? py_w : pz_w;
        g_tcat[t] = s[oo * Cc + k]; return;
    }
    t -= 36864;
    if (t < Cc) {
        const float* s = (t < 64) ? px_b : (t < 128) ? py_b : pz_b;
        g_bcat[t] = s[t & 63]; return;
    }
    t -= Cc;
    if (t < 73728) { int k = t / 192, n = t % 192;
        g_tx[t] = (n < 140) ? x_proj_w[n * DIN + k] : 0.f; return; }
    t -= 73728;
    if (t < 73728) { int k = t / Cc, n = t % Cc; g_tout[t] = out_proj_w[n * DIN + k]; return; }
    t -= 73728;
    if (t < 331776) {
        int tap = t / (Cc * 64); int rem = t % (Cc * 64); int c = rem / 64, o = rem & 63;
        g_tw1[t] = (o < 48) ? off_w1[(o * Cc + c) * 27 + tap] : 0.f; return;
    }
}

// ---------------- tiled transpose x -> g_xT ----------------
__global__ void xt_kernel(const float* __restrict__ x) {
    __shared__ float tile[32][33];
    int l0 = blockIdx.x * 32, c0 = blockIdx.y * 32, b = blockIdx.z;
    int tx = threadIdx.x & 31, ty = threadIdx.x >> 5;
    #pragma unroll
    for (int i = 0; i < 32; i += 8)
        tile[ty + i][tx] = x[(b * Cc + c0 + ty + i) * LL + l0 + tx];
    __syncthreads();
    #pragma unroll
    for (int i = 0; i < 32; i += 8)
        g_xT[(b * LL + l0 + ty + i) * Cc + c0 + tx] = tile[tx][ty + i];
}

// ---------------- mean over last dim ----------------
__global__ void mean_kernel(const float* __restrict__ in, float* __restrict__ out) {
    int bc = blockIdx.x;
    const float* p = in + bc * LL;
    float s = 0.f;
    for (int i = threadIdx.x; i < LL; i += 256) s += p[i];
    __shared__ float sm[256];
    sm[threadIdx.x] = s; __syncthreads();
    for (int st = 128; st > 0; st >>= 1) {
        if (threadIdx.x < st) sm[threadIdx.x] += sm[threadIdx.x + st];
        __syncthreads();
    }
    if (threadIdx.x == 0) out[bc] = sm[0] * (1.f / (float)LL);
}

// ---------------- branch gate weights ----------------
__global__ void wts_kernel(const float* __restrict__ wg_w, const float* __restrict__ wg_b) {
    int b = blockIdx.x;
    int i = threadIdx.x >> 5;
    int lane = threadIdx.x & 31;
    float s = 0.f;
    for (int c = lane; c < Cc; c += 32) s += g_pooled[b * Cc + c] * wg_w[i * Cc + c];
    for (int off = 16; off; off >>= 1) s += __shfl_xor_sync(0xffffffffu, s, off);
    __shared__ float lg[3];
    if (lane == 0) lg[i] = s + wg_b[i];
    __syncthreads();
    if (threadIdx.x == 0) {
        float m = fmaxf(lg[0], fmaxf(lg[1], lg[2]));
        float e0 = expf(lg[0] - m), e1 = expf(lg[1] - m), e2 = expf(lg[2] - m);
        float inv = 1.f / (e0 + e1 + e2);
        g_wts[b * 3 + 0] = e0 * inv;
        g_wts[b * 3 + 1] = e1 * inv;
        g_wts[b * 3 + 2] = e2 * inv;
    }
}

// ---------------- conv1 implicit GEMM: grid (64 m-tiles, 27 taps) ----------------
__global__ void conv1_kernel() {
    __shared__ float sA[64][66];
    __shared__ float sW[64][72];
    int m0 = blockIdx.x * 64;
    int tap = blockIdx.y;
    int kd = tap / 9, kh = (tap / 3) % 3, kw = tap % 3;
    int loff = (kd - 1) * 256 + (kh - 1) * 16 + (kw - 1);
    int tid = threadIdx.x;
    int tn = tid & 7, tm = tid >> 3;
    float acc[4][8] = {};
    for (int k0 = 0; k0 < Cc; k0 += 64) {
        #pragma unroll
        for (int t = 0; t < 16; ++t) {
            int idx = tid + t * 128;
            int r = idx >> 5, c2 = idx & 31;
            int ll = (m0 & 1023) + r;
            int z = ll >> 8, y = (ll >> 4) & 15, xx = ll & 15;
            bool ok = ((unsigned)(z + kd - 1) < 4u) && ((unsigned)(y + kh - 1) < 16u)
                   && ((unsigned)(xx + kw - 1) < 16u);
            float2 v = make_float2(0.f, 0.f);
            if (ok) v = *(const float2*)&g_xT[(m0 + r + loff) * Cc + k0 + c2 * 2];
            *(float2*)&sA[r][c2 * 2] = v;
        }
        #pragma unroll
        for (int t = 0; t < 8; ++t) {
            int idx = tid + t * 128;
            int r = idx >> 4, c4 = idx & 15;
            *(float4*)&sW[r][c4 * 4] = *(const float4*)&g_tw1[(tap * Cc + k0 + r) * 64 + c4 * 4];
        }
        __syncthreads();
        #pragma unroll
        for (int k = 0; k < 64; ++k) {
            float a0 = sA[tm * 4 + 0][k], a1 = sA[tm * 4 + 1][k];
            float a2 = sA[tm * 4 + 2][k], a3 = sA[tm * 4 + 3][k];
            float4 wlo = *(const float4*)&sW[k][tn * 4];
            float4 whi = *(const float4*)&sW[k][32 + tn * 4];
            acc[0][0] += a0*wlo.x; acc[0][1] += a0*wlo.y; acc[0][2] += a0*wlo.z; acc[0][3] += a0*wlo.w;
            acc[0][4] += a0*whi.x; acc[0][5] += a0*whi.y; acc[0][6] += a0*whi.z; acc[0][7] += a0*whi.w;
            acc[1][0] += a1*wlo.x; acc[1][1] += a1*wlo.y; acc[1][2] += a1*wlo.z; acc[1][3] += a1*wlo.w;
            acc[1][4] += a1*whi.x; acc[1][5] += a1*whi.y; acc[1][6] += a1*whi.z; acc[1][7] += a1*whi.w;
            acc[2][0] += a2*wlo.x; acc[2][1] += a2*wlo.y; acc[2][2] += a2*wlo.z; acc[2][3] += a2*wlo.w;
            acc[2][4] += a2*whi.x; acc[2][5] += a2*whi.y; acc[2][6] += a2*whi.z; acc[2][7] += a2*whi.w;
            acc[3][0] += a3*wlo.x; acc[3][1] += a3*wlo.y; acc[3][2] += a3*wlo.z; acc[3][3] += a3*wlo.w;
            acc[3][4] += a3*whi.x; acc[3][5] += a3*whi.y; acc[3][6] += a3*whi.z; acc[3][7] += a3*whi.w;
        }
        __syncthreads();
    }
    float* dst = g_hidp + tap * HIDN;
    #pragma unroll
    for (int i = 0; i < 4; ++i) {
        int l = m0 + tm * 4 + i;
        float4 lo = make_float4(acc[i][0], acc[i][1], acc[i][2], acc[i][3]);
        *(float4*)&dst[l * 48 + tn * 4] = lo;
        if (tn < 4) {
            float4 hi = make_float4(acc[i][4], acc[i][5], acc[i][6], acc[i][7]);
            *(float4*)&dst[l * 48 + 32 + tn * 4] = hi;
        }
    }
}

// ---------------- reduce 27 tap partials + bias + gelu -> g_hidT [bl][48] ----------------
__global__ void hidred_kernel(const float* __restrict__ b1) {
    int t = blockIdx.x * 256 + threadIdx.x;
    if (t >= HIDN) return;
    float s = b1[t % 48];
    #pragma unroll
    for (int k = 0; k < 27; ++k) s += g_hidp[k * HIDN + t];
    g_hidT[t] = geluf_(s);
}

// ---------------- conv2: one warp per voxel ----------------
__global__ void conv2_kernel(const float* __restrict__ w2, const float* __restrict__ b2) {
    __shared__ float ws[3 * 48 * 27];
    int tid = threadIdx.x;
    for (int i = tid; i < 3 * 48 * 27; i += 128) ws[i] = w2[i];
    __syncthreads();
    int lane = tid & 31, warpid = tid >> 5;
    int bl = blockIdx.x * 4 + warpid;
    int ll = bl & 1023;
    int z = ll >> 8, y = (ll >> 4) & 15, xx = ll & 15;
    int c2 = 32 + (lane & 15);                  // safe second channel index (<48)
    float m2 = (lane < 16) ? 1.f : 0.f;
    float s0 = 0.f, s1 = 0.f, s2 = 0.f;
    #pragma unroll
    for (int tap = 0; tap < 27; ++tap) {
        int kd = tap / 9, kh = (tap / 3) % 3, kw = tap % 3;
        bool ok = ((unsigned)(z + kd - 1) < 4u) && ((unsigned)(y + kh - 1) < 16u)
               && ((unsigned)(xx + kw - 1) < 16u);
        if (ok) {
            int bl2 = bl + (kd - 1) * 256 + (kh - 1) * 16 + (kw - 1);
            float h0 = g_hidT[bl2 * 48 + lane];
            float h1 = m2 * g_hidT[bl2 * 48 + c2 - ((lane < 16) ? 0 : 16)];
            // note: for lane>=16 h1 is zeroed; index stays in-bounds
            s0 += h0 * ws[(0 * 48 + lane) * 27 + tap] + h1 * ws[(0 * 48 + c2) * 27 + tap];
            s1 += h0 * ws[(1 * 48 + lane) * 27 + tap] + h1 * ws[(1 * 48 + c2) * 27 + tap];
            s2 += h0 * ws[(2 * 48 + lane) * 27 + tap] + h1 * ws[(2 * 48 + c2) * 27 + tap];
        }
    }
    #pragma unroll
    for (int off = 16; off; off >>= 1) {
        s0 += __shfl_xor_sync(0xffffffffu, s0, off);
        s1 += __shfl_xor_sync(0xffffffffu, s1, off);
        s2 += __shfl_xor_sync(0xffffffffu, s2, off);
    }
    if (lane == 0) {
        g_offs[bl * 3 + 0] = s0 + b2[0];
        g_offs[bl * 3 + 1] = s1 + b2[1];
        g_offs[bl * 3 + 2] = s2 + b2[2];
    }
}

// ---------------- pos-emb grid sample -> g_xs ----------------
__global__ void posemb_kernel() {
    int bl = blockIdx.x;
    int b = bl >> 10;
    int c = threadIdx.x;
    float gx = g_offs[bl * 3 + 0];
    float gy = g_offs[bl * 3 + 1];
    float gz = g_offs[bl * 3 + 2];
    float ixf = ((gx + 1.f) * (float)Ww - 1.f) * 0.5f;
    float iyf = ((gy + 1.f) * (float)Hh - 1.f) * 0.5f;
    float izf = ((gz + 1.f) * (float)Dd - 1.f) * 0.5f;
    float x0 = floorf(ixf), y0 = floorf(iyf), z0 = floorf(izf);
    float pe = 0.f;
    #pragma unroll
    for (int dz = 0; dz < 2; ++dz)
    #pragma unroll
    for (int dy = 0; dy < 2; ++dy)
    #pragma unroll
    for (int dx = 0; dx < 2; ++dx) {
        float xc = x0 + dx, yc = y0 + dy, zc = z0 + dz;
        float wgt = (1.f - fabsf(ixf - xc)) * (1.f - fabsf(iyf - yc)) * (1.f - fabsf(izf - zc));
        bool valid = (xc >= 0.f) && (xc < (float)Ww) && (yc >= 0.f) && (yc < (float)Hh)
                  && (zc >= 0.f) && (zc < (float)Dd);
        int xi_ = (int)fminf(fmaxf(xc, 0.f), (float)(Ww - 1));
        int yi_ = (int)fminf(fmaxf(yc, 0.f), (float)(Hh - 1));
        int zi_ = (int)fminf(fmaxf(zc, 0.f), (float)(Dd - 1));
        int idx = (zi_ * Hh + yi_) * Ww + xi_;
        pe += g_xT[(b * LL + idx) * Cc + c] * wgt * (valid ? 1.f : 0.f);
    }
    g_xs[bl * Cc + c] = pe;
}

// ---------------- conflict-free tiled GEMM: C = A[M][K] @ Wt[K][NP] ----------------
// grid (M/64, NP/64), block 128. EPI 0: plain (guard NR)  1: (+bias)*wts += g_xs  2: transposed out
template<int K, int NP, int NR, int EPI>
__global__ void gemm64(const float* __restrict__ A, const float* __restrict__ Wt,
                       float* __restrict__ outp) {
    __shared__ float sA[64][66];
    __shared__ float sW[64][72];
    int m0 = blockIdx.x * 64;
    int n0 = blockIdx.y * 64;
    int tid = threadIdx.x;
    int tn = tid & 7, tm = tid >> 3;
    float acc[4][8] = {};
    for (int k0 = 0; k0 < K; k0 += 64) {
        #pragma unroll
        for (int t = 0; t < 16; ++t) {
            int idx = tid + t * 128;
            int r = idx >> 5, c2 = idx & 31;
            *(float2*)&sA[r][c2 * 2] = *(const float2*)&A[(m0 + r) * K + k0 + c2 * 2];
        }
        #pragma unroll
        for (int t = 0; t < 8; ++t) {
            int idx = tid + t * 128;
            int r = idx >> 4, c4 = idx & 15;
            *(float4*)&sW[r][c4 * 4] = *(const float4*)&Wt[(k0 + r) * NP + n0 + c4 * 4];
        }
        __syncthreads();
        #pragma unroll
        for (int k = 0; k < 64; ++k) {
            float a0 = sA[tm * 4 + 0][k], a1 = sA[tm * 4 + 1][k];
            float a2 = sA[tm * 4 + 2][k], a3 = sA[tm * 4 + 3][k];
            float4 wlo = *(const float4*)&sW[k][tn * 4];
            float4 whi = *(const float4*)&sW[k][32 + tn * 4];
            acc[0][0] += a0*wlo.x; acc[0][1] += a0*wlo.y; acc[0][2] += a0*wlo.z; acc[0][3] += a0*wlo.w;
            acc[0][4] += a0*whi.x; acc[0][5] += a0*whi.y; acc[0][6] += a0*whi.z; acc[0][7] += a0*whi.w;
            acc[1][0] += a1*wlo.x; acc[1][1] += a1*wlo.y; acc[1][2] += a1*wlo.z; acc[1][3] += a1*wlo.w;
            acc[1][4] += a1*whi.x; acc[1][5] += a1*whi.y; acc[1][6] += a1*whi.z; acc[1][7] += a1*whi.w;
            acc[2][0] += a2*wlo.x; acc[2][1] += a2*wlo.y; acc[2][2] += a2*wlo.z; acc[2][3] += a2*wlo.w;
            acc[2][4] += a2*whi.x; acc[2][5] += a2*whi.y; acc[2][6] += a2*whi.z; acc[2][7] += a2*whi.w;
            acc[3][0] += a3*wlo.x; acc[3][1] += a3*wlo.y; acc[3][2] += a3*wlo.z; acc[3][3] += a3*wlo.w;
            acc[3][4] += a3*whi.x; acc[3][5] += a3*whi.y; acc[3][6] += a3*whi.z; acc[3][7] += a3*whi.w;
        }
        __syncthreads();
    }
    if (EPI == 0) {
        #pragma unroll
        for (int i = 0; i < 4; ++i) {
            int l = m0 + tm * 4 + i;
            if (NP == NR) {
                *(float4*)&outp[l * NR + n0 + tn * 4] =
                    make_float4(acc[i][0], acc[i][1], acc[i][2], acc[i][3]);
                *(float4*)&outp[l * NR + n0 + 32 + tn * 4] =
                    make_float4(acc[i][4], acc[i][5], acc[i][6], acc[i][7]);
            } else {
                #pragma unroll
                for (int j = 0; j < 4; ++j) {
                    int n = n0 + tn * 4 + j;
                    if (n < NR) outp[l * NR + n] = acc[i][j];
                    int n2 = n0 + 32 + tn * 4 + j;
                    if (n2 < NR) outp[l * NR + n2] = acc[i][j + 4];
                }
            }
        }
    } else if (EPI == 1) {
        float wt = g_wts[(m0 >> 10) * 3 + (n0 >> 6)];
        #pragma unroll
        for (int i = 0; i < 4; ++i) {
            int l = m0 + tm * 4 + i;
            int base = l * Cc + n0 + tn * 4;
            float4 cur = *(const float4*)&outp[base];
            cur.x += (acc[i][0] + g_bcat[n0 + tn * 4 + 0]) * wt;
            cur.y += (acc[i][1] + g_bcat[n0 + tn * 4 + 1]) * wt;
            cur.z += (acc[i][2] + g_bcat[n0 + tn * 4 + 2]) * wt;
            cur.w += (acc[i][3] + g_bcat[n0 + tn * 4 + 3]) * wt;
            *(float4*)&outp[base] = cur;
            int base2 = l * Cc + n0 + 32 + tn * 4;
            float4 cur2 = *(const float4*)&outp[base2];
            cur2.x += (acc[i][4] + g_bcat[n0 + 32 + tn * 4 + 0]) * wt;
            cur2.y += (acc[i][5] + g_bcat[n0 + 32 + tn * 4 + 1]) * wt;
            cur2.z += (acc[i][6] + g_bcat[n0 + 32 + tn * 4 + 2]) * wt;
            cur2.w += (acc[i][7] + g_bcat[n0 + 32 + tn * 4 + 3]) * wt;
            *(float4*)&outp[base2] = cur2;
        }
    } else {
        // transposed store via smem staging (reuse sW: 64x72 >= 64x68)
        float* sT = &sW[0][0];
        #pragma unroll
        for (int i = 0; i < 4; ++i) {
            int ml = tm * 4 + i;
            #pragma unroll
            for (int j = 0; j < 4; ++j) {
                sT[(tn * 4 + j) * 68 + ml] = acc[i][j];
                sT[(32 + tn * 4 + j) * 68 + ml] = acc[i][j + 4];
            }
        }
        __syncthreads();
        int b = m0 >> 10, l0 = m0 & 1023;
        #pragma unroll
        for (int t = 0; t < 8; ++t) {
            int idx = tid + t * 128;
            int nr = idx >> 4, c4 = idx & 15;
            float4 v = *(const float4*)&sT[nr * 68 + c4 * 4];
            *(float4*)&outp[((b * Cc + n0 + nr) << 10) + l0 + c4 * 4] = v;
        }
    }
}

// ---------------- depthwise causal conv + silu ----------------
__global__ void dwconv_kernel(const float* __restrict__ cw, const float* __restrict__ cb) {
    int t = blockIdx.x * blockDim.x + threadIdx.x;
    if (t >= MM * DIN) return;
    int d = t % DIN; int bl = t / DIN; int l = bl % LL; int b = bl / LL;
    const float* base = g_xz + (b * LL) * (2 * DIN) + d;
    float s = cb[d];
    #pragma unroll
    for (int k = 0; k < DCONV; ++k) {
        int ll = l - (DCONV - 1) + k;
        if (ll >= 0) s += base[ll * (2 * DIN)] * cw[d * DCONV + k];
    }
    g_xi[t] = s * sigmoidf_(s);
}

// ---------------- delta ----------------
__global__ void delta_kernel(const float* __restrict__ dtw, const float* __restrict__ dtb) {
    __shared__ float sdt[DIN * DTRANK];
    int tid = threadIdx.x;
    for (int k = tid; k < DIN * DTRANK; k += 256) sdt[k] = dtw[k];
    __syncthreads();
    int t = blockIdx.x * 256 + tid;
    if (t >= MM * DIN) return;
    int d = t % DIN; int bl = t / DIN;
    const float* row = g_dbl + bl * 140;
    float s = dtb[d];
    #pragma unroll
    for (int r = 0; r < DTRANK; ++r) s += row[r] * sdt[d * DTRANK + r];
    g_delta[t] = softplusf_(s);
}

// ---------------- selective scan ----------------
__global__ void scan_kernel(const float* __restrict__ a_log, const float* __restrict__ Dskip) {
    int warp = (blockIdx.x * blockDim.x + threadIdx.x) >> 5;
    int lane = threadIdx.x & 31;
    if (warp >= Bn * DIN) return;
    int b = warp / DIN, d = warp % DIN;
    float a0 = -expf(a_log[d * DSTATE + lane]);
    float a1 = -expf(a_log[d * DSTATE + 32 + lane]);
    float dsk = Dskip[d];
    float h0 = 0.f, h1 = 0.f;
    const float* dptr = g_delta + b * LL * DIN + d;
    const float* uptr = g_xi + b * LL * DIN + d;
    const float* dblb = g_dbl + b * LL * 140;
    const float* zptr = g_xz + b * LL * (2 * DIN) + DIN + d;
    float* yo = g_y + b * LL * DIN + d;
    #pragma unroll 4
    for (int l = 0; l < LL; ++l) {
        float dt = __ldg(dptr + l * DIN);
        float u = __ldg(uptr + l * DIN);
        const float* row = dblb + l * 140;
        float b0 = __ldg(row + 12 + lane), b1v = __ldg(row + 44 + lane);
        float c0 = __ldg(row + 76 + lane), c1 = __ldg(row + 108 + lane);
        float du = dt * u;
        h0 = __expf(dt * a0) * h0 + du * b0;
        h1 = __expf(dt * a1) * h1 + du * b1v;
        float part = h0 * c0 + h1 * c1;
        #pragma unroll
        for (int off = 16; off; off >>= 1) part += __shfl_xor_sync(0xffffffffu, part, off);
        if (lane == 0) {
            float z = __ldg(zptr + l * (2 * DIN));
            yo[l * DIN] = (part + u * dsk) * (z * sigmoidf_(z));
        }
    }
}

// ---------------- channel attention ----------------
__global__ void ca_kernel(const float* __restrict__ w1, const float* __restrict__ b1,
                          const float* __restrict__ w2, const float* __restrict__ b2) {
    int b = blockIdx.x;
    int tid = threadIdx.x;
    __shared__ float p[Cc];
    __shared__ float hid[48];
    p[tid] = g_p2[b * Cc + tid];
    __syncthreads();
    if (tid < 48) {
        const float* wr = w1 + tid * Cc;
        float s = b1[tid];
        for (int k = 0; k < Cc; ++k) s += p[k] * wr[k];
        hid[tid] = geluf_(s);
    }
    __syncthreads();
    const float* wr2 = w2 + tid * 48;
    float s = b2[tid];
    #pragma unroll
    for (int j = 0; j < 48; ++j) s += hid[j] * wr2[j];
    g_attn[b * Cc + tid] = sigmoidf_(s);
}

__global__ void scale_kernel(float* __restrict__ out) {
    int t = blockIdx.x * blockDim.x + threadIdx.x;
    if (t >= Bn * Cc * LL) return;
    out[t] *= g_attn[t / LL];
}

extern "C" void kernel_launch(void* const* d_in, const int* in_sizes, int n_in,
                              void* d_out, int out_size) {
    const float* x         = (const float*)d_in[0];
    const float* px_w      = (const float*)d_in[1];
    const float* px_b      = (const float*)d_in[2];
    const float* py_w      = (const float*)d_in[3];
    const float* py_b      = (const float*)d_in[4];
    const float* pz_w      = (const float*)d_in[5];
    const float* pz_b      = (const float*)d_in[6];
    const float* wg_w      = (const float*)d_in[7];
    const float* wg_b      = (const float*)d_in[8];
    const float* off_w1    = (const float*)d_in[9];
    const float* off_b1    = (const float*)d_in[10];
    const float* off_w2    = (const float*)d_in[11];
    const float* off_b2    = (const float*)d_in[12];
    const float* in_proj_w = (const float*)d_in[13];
    const float* conv_w    = (const float*)d_in[14];
    const float* conv_b    = (const float*)d_in[15];
    const float* x_proj_w  = (const float*)d_in[16];
    const float* dt_proj_w = (const float*)d_in[17];
    const float* dt_proj_b = (const float*)d_in[18];
    const float* A_log     = (const float*)d_in[19];
    const float* D_skip    = (const float*)d_in[20];
    const float* out_proj_w = (const float*)d_in[21];
    const float* ca_w1     = (const float*)d_in[22];
    const float* ca_b1     = (const float*)d_in[23];
    const float* ca_w2     = (const float*)d_in[24];
    const float* ca_b2     = (const float*)d_in[25];
    float* out = (float*)d_out;

    float *g_pooled_p, *g_p2_p, *g_xT_p, *g_xs_p, *g_xz_p, *g_xi_p, *g_dbl_p, *g_y_p;
    float *g_tin_p, *g_tcat_p, *g_tx_p, *g_tout_p;
    cudaGetSymbolAddress((void**)&g_pooled_p, g_pooled);
    cudaGetSymbolAddress((void**)&g_p2_p, g_p2);
    cudaGetSymbolAddress((void**)&g_xT_p, g_xT);
    cudaGetSymbolAddress((void**)&g_xs_p, g_xs);
    cudaGetSymbolAddress((void**)&g_xz_p, g_xz);
    cudaGetSymbolAddress((void**)&g_xi_p, g_xi);
    cudaGetSymbolAddress((void**)&g_dbl_p, g_dbl);
    cudaGetSymbolAddress((void**)&g_y_p, g_y);
    cudaGetSymbolAddress((void**)&g_tin_p, g_tin);
    cudaGetSymbolAddress((void**)&g_tcat_p, g_tcat);
    cudaGetSymbolAddress((void**)&g_tx_p, g_tx);
    cudaGetSymbolAddress((void**)&g_tout_p, g_tout);

    prep_kernel<<<(663744 + 255) / 256, 256>>>(in_proj_w, px_w, py_w, pz_w, px_b, py_b, pz_b,
                                               x_proj_w, out_proj_w, off_w1);
    xt_kernel<<<dim3(32, 6, 4), 256>>>(x);
    mean_kernel<<<Bn * Cc, 256>>>(x, g_pooled_p);
    wts_kernel<<<Bn, 96>>>(wg_w, wg_b);
    conv1_kernel<<<dim3(64, 27), 128>>>();
    hidred_kernel<<<(HIDN + 255) / 256, 256>>>(off_b1);
    conv2_kernel<<<MM / 4, 128>>>(off_w2, off_b2);
    posemb_kernel<<<MM, Cc>>>();
    gemm64<Cc, Cc, Cc, 1><<<dim3(64, 3), 128>>>(g_xT_p, g_tcat_p, g_xs_p);
    gemm64<Cc, 768, 768, 0><<<dim3(64, 12), 128>>>(g_xs_p, g_tin_p, g_xz_p);
    dwconv_kernel<<<(MM * DIN + 255) / 256, 256>>>(conv_w, conv_b);
    gemm64<DIN, 192, 140, 0><<<dim3(64, 3), 128>>>(g_xi_p, g_tx_p, g_dbl_p);
    delta_kernel<<<(MM * DIN + 255) / 256, 256>>>(dt_proj_w, dt_proj_b);
    scan_kernel<<<(Bn * DIN * 32 + 127) / 128, 128>>>(A_log, D_skip);
    gemm64<DIN, Cc, Cc, 2><<<dim3(64, 3), 128>>>(g_y_p, g_tout_p, out);
    mean_kernel<<<Bn * Cc, 256>>>(out, g_p2_p);
    ca_kernel<<<Bn, Cc>>>(ca_w1, ca_b1, ca_w2, ca_b2);
    scale_kernel<<<(Bn * Cc * LL + 255) / 256, 256>>>(out);
}